// round 13
// baseline (speedup 1.0000x reference)
#include <cuda_runtime.h>
#include <cuda_fp16.h>
#include <math.h>

#define T_   4
#define B_   32
#define C_   384
#define N_   196
#define H_   12
#define D_   32
#define CN_  (C_*N_)            // 75264
#define BCN  (B_*C_*N_)         // 2408448
#define TBCN (T_*B_*C_*N_)      // 9633792
#define JTOT (B_*N_*T_)         // 25088 tokens
#define BNJ  (B_*N_)            // 6272
#define WQKV (1152*384)         // 442368
#define WPRJ (384*384)          // 147456
#define INV2048 4.8828125e-4f

// ---------------- scratch (device globals; no allocation allowed) ------------
__device__ float g_qkv[3u * TBCN];        // q,k,v preact -> spikes (in place); proj scratch
__device__ float g_att[TBCN];             // attention out (preact)
__device__ __half g_xs[2u * TBCN];        // split X: [part][j][c] K-major
__device__ __half g_ss[TBCN];             // proj spike input, [j][c] K-major (exact)
__device__ __half g_ws[2u * WQKV];        // split qkv weights [part][o][c]
__device__ __half g_ps[2u * WPRJ];        // split proj weights
__device__ float g_bnscale[3 * C_];
__device__ float g_bnbias[3 * C_];
__device__ float g_pscale[C_];
__device__ float g_pbias[C_];

// ---------------- helpers ------------------------------------------------------
__device__ __forceinline__ unsigned smem_to_u32(const void* p) {
    unsigned a;
    asm("{ .reg .u64 t; cvta.to.shared.u64 t, %1; cvt.u32.u64 %0, t; }"
        : "=r"(a) : "l"(p));
    return a;
}
__device__ __forceinline__ void ldsm4(unsigned& r0, unsigned& r1,
                                      unsigned& r2, unsigned& r3, unsigned addr) {
    asm volatile("ldmatrix.sync.aligned.m8n8.x4.shared.b16 {%0,%1,%2,%3}, [%4];"
        : "=r"(r0), "=r"(r1), "=r"(r2), "=r"(r3) : "r"(addr));
}
__device__ __forceinline__ void mma16816h(float* c, const unsigned* a, const unsigned* b) {
    asm volatile(
        "mma.sync.aligned.m16n8k16.row.col.f32.f16.f16.f32 "
        "{%0,%1,%2,%3}, {%4,%5,%6,%7}, {%8,%9}, {%0,%1,%2,%3};"
        : "+f"(c[0]), "+f"(c[1]), "+f"(c[2]), "+f"(c[3])
        : "r"(a[0]), "r"(a[1]), "r"(a[2]), "r"(a[3]), "r"(b[0]), "r"(b[1]));
}
__device__ __forceinline__ void cpasync16(unsigned dst, const void* src) {
    asm volatile("cp.async.cg.shared.global [%0], [%1], 16;"
        :: "r"(dst), "l"(src) : "memory");
}
#define CP_COMMIT() asm volatile("cp.async.commit_group;" ::: "memory")
#define CP_WAIT1()  asm volatile("cp.async.wait_group 1;" ::: "memory")
__device__ __forceinline__ void split2h(float x, __half& h, __half& m) {
    h = __float2half_rn(x);
    float r = x - __half2float(h);
    m = __float2half_rn(r * 2048.0f);    // scaled residual: always normal range
}
// f32x2 packed math
__device__ __forceinline__ unsigned long long pack2(float lo, float hi) {
    unsigned long long d;
    asm("mov.b64 %0, {%1, %2};" : "=l"(d) : "f"(lo), "f"(hi));
    return d;
}
__device__ __forceinline__ void fma2(unsigned long long& d,
                                     unsigned long long a, unsigned long long b) {
    asm("fma.rn.f32x2 %0, %1, %2, %3;" : "=l"(d) : "l"(a), "l"(b), "l"(d));
}
__device__ __forceinline__ void unpack2(unsigned long long v, float& lo, float& hi) {
    asm("mov.b64 {%0, %1}, %2;" : "=f"(lo), "=f"(hi) : "l"(v));
}

// ---------------- BN coefficient setup ---------------------------------------
__global__ void setup_bn(
    const float* __restrict__ qg, const float* __restrict__ qb, const float* __restrict__ qm, const float* __restrict__ qv,
    const float* __restrict__ kg, const float* __restrict__ kb, const float* __restrict__ km, const float* __restrict__ kv,
    const float* __restrict__ vg, const float* __restrict__ vb, const float* __restrict__ vm, const float* __restrict__ vv,
    const float* __restrict__ pg, const float* __restrict__ pb, const float* __restrict__ pm, const float* __restrict__ pv,
    const float* __restrict__ pbias)
{
    int i = blockIdx.x * blockDim.x + threadIdx.x;
    if (i < 3 * C_) {
        int p = i / C_, c = i - p * C_;
        const float *g, *be, *mu, *va;
        if (p == 0)      { g = qg; be = qb; mu = qm; va = qv; }
        else if (p == 1) { g = kg; be = kb; mu = km; va = kv; }
        else             { g = vg; be = vb; mu = vm; va = vv; }
        float inv = g[c] / sqrtf(va[c] + 1e-5f);
        g_bnscale[i] = inv;
        g_bnbias[i]  = be[c] - mu[c] * inv;
    } else if (i < 4 * C_) {
        int c = i - 3 * C_;
        float inv = pg[c] / sqrtf(pv[c] + 1e-5f);
        g_pscale[c] = inv;
        g_pbias[c]  = pb[c] - pm[c] * inv + pbias[c] * inv;
    }
}

// ---------------- weight split (qkv stacked 1152 rows + proj 384) -------------
__global__ void wsplit(const float* __restrict__ qw, const float* __restrict__ kw,
                       const float* __restrict__ vw, const float* __restrict__ pw)
{
    int i = blockIdx.x * blockDim.x + threadIdx.x;
    if (i < WQKV) {
        int o = i / 384, c = i - o * 384;
        const float* w = (o < 384) ? qw : ((o < 768) ? kw : vw);
        float x = w[(o % 384) * 384 + c];
        __half h, m;
        split2h(x, h, m);
        g_ws[i] = h; g_ws[WQKV + i] = m;
    } else if (i < WQKV + WPRJ) {
        int k = i - WQKV;
        __half h, m;
        split2h(pw[k], h, m);
        g_ps[k] = h; g_ps[WPRJ + k] = m;
    }
}

// ---------------- X split + transpose to [j][c] K-major -----------------------
__global__ __launch_bounds__(256) void xsplit(const float* __restrict__ X)
{
    __shared__ float tile[64 * 65];
    __shared__ int cb[64];
    int tid = threadIdx.x;
    int j0 = blockIdx.x * 64, c0 = blockIdx.y * 64;
    if (tid < 64) {
        int j = j0 + tid;
        int t = j / (B_ * N_);
        int r = j - t * (B_ * N_);
        int b = r / N_;
        int n = r - b * N_;
        cb[tid] = (t * B_ + b) * CN_ + n;
    }
    __syncthreads();
#pragma unroll
    for (int u = 0; u < 16; ++u) {
        int idx = u * 256 + tid;
        int cc = idx >> 6, jj = idx & 63;
        tile[cc * 65 + jj] = X[(size_t)cb[jj] + (size_t)(c0 + cc) * N_];
    }
    __syncthreads();
#pragma unroll
    for (int u = 0; u < 16; ++u) {
        int idx = u * 256 + tid;
        int jj = idx >> 6, cc = idx & 63;
        __half h, m;
        split2h(tile[cc * 65 + jj], h, m);
        size_t o = (size_t)(j0 + jj) * 384 + c0 + cc;
        g_xs[o] = h; g_xs[TBCN + o] = m;
    }
}

// -------- fused LIF(thr=0.5) + spike transpose to [j][c] fp16 (exact) ---------
// In: att preact [t][b][c][n]. Out: g_ss[(t*BNJ + b*196 + n)*384 + c] spikes.
// Block: 64 (b,n) x 64 c tile; loops t with membrane state in regs.
__global__ __launch_bounds__(256) void lif_strans(const float* __restrict__ S)
{
    __shared__ float tile[64 * 65];
    __shared__ int cb[64];
    int tid = threadIdx.x;
    int bn0 = blockIdx.x * 64, c0 = blockIdx.y * 64;
    if (tid < 64) {
        int bn = bn0 + tid;
        int b = bn / N_;
        int n = bn - b * N_;
        cb[tid] = b * CN_ + n;
    }
    __syncthreads();

    float v[16];
#pragma unroll
    for (int u = 0; u < 16; ++u) v[u] = 0.0f;

    for (int t = 0; t < T_; ++t) {
        const float* St = S + (size_t)t * BCN;
#pragma unroll
        for (int u = 0; u < 16; ++u) {
            int idx = u * 256 + tid;
            int cc = idx >> 6, jj = idx & 63;
            float x = St[(size_t)cb[jj] + (size_t)(c0 + cc) * N_];
            float vv = v[u] + (x - v[u]) * 0.5f;
            float s = (vv >= 0.5f) ? 1.0f : 0.0f;
            v[u] = (s != 0.f) ? 0.f : vv;
            tile[cc * 65 + jj] = s;
        }
        __syncthreads();
        __half* out = g_ss + (size_t)(t * BNJ) * 384;
#pragma unroll
        for (int u = 0; u < 16; ++u) {
            int idx = u * 256 + tid;
            int jj = idx >> 6, cc = idx & 63;
            out[(size_t)(bn0 + jj) * 384 + c0 + cc] = __float2half_rn(tile[cc * 65 + jj]);
        }
        __syncthreads();
    }
}

// ---------------- tensor-core GEMM (fp16 2-term split, cp.async 2-stage) ------
// D[o,j] = sum_c W[o,c]*X[j,c]; W = h + m*2^-11 (m stored scaled by 2^11).
// NBP=2: X split too (acc0 += hh; acc1 += hm + mh). NBP=1: X exact
// (acc0 += hX; acc1 += mX). Final: acc0 + 2^-11*acc1.
// Tile 64(o) x 128(j), BK=64 (6 chunks), 2-stage cp.async double buffer.
#define TPAD   144               // 128B data + 16B pad: conflict-free ldmatrix
#define ATB    (64 * TPAD)       // 9216
#define BTB    (128 * TPAD)      // 18432
#define NCH    6

template <int NBP>
__device__ __forceinline__ void stage_load(
    unsigned sb, const __half* __restrict__ A, size_t APS,
    const __half* __restrict__ Bm, size_t BPS,
    int o0, int j0, int c0, int r8, int g8)
{
#pragma unroll
    for (int p = 0; p < 2; ++p) {
#pragma unroll
        for (int u = 0; u < 2; ++u) {
            int row = r8 + u * 32;
            const __half* src = A + (size_t)p * APS + (size_t)(o0 + row) * 384 + c0 + g8 * 8;
            cpasync16(sb + p * ATB + row * TPAD + g8 * 16, src);
        }
    }
#pragma unroll
    for (int p = 0; p < NBP; ++p) {
#pragma unroll
        for (int u = 0; u < 4; ++u) {
            int row = r8 + u * 32;
            const __half* src = Bm + (size_t)p * BPS + (size_t)(j0 + row) * 384 + c0 + g8 * 8;
            cpasync16(sb + 2 * ATB + p * BTB + row * TPAD + g8 * 16, src);
        }
    }
}

template <int NBP>
__global__ __launch_bounds__(256) void gemm_mma(
    const __half* __restrict__ A, size_t APS,
    const __half* __restrict__ Bm, size_t BPS,
    const float* __restrict__ scale, const float* __restrict__ bias,
    float* __restrict__ Y)
{
    constexpr int STGB = 2 * ATB + NBP * BTB;
    extern __shared__ __align__(16) char dsm[];
    __shared__ int sbase[128];
    unsigned smt = smem_to_u32(dsm);

    int tid = threadIdx.x;
    int wid = tid >> 5, lane = tid & 31;
    int wm = wid & 1, wn = wid >> 1;
    int j0 = blockIdx.x * 128;
    int o0 = blockIdx.y * 64;

    if (tid < 128) {
        int j = j0 + tid;
        int t = j / (B_ * N_);
        int r = j - t * (B_ * N_);
        int b = r / N_;
        int n = r - b * N_;
        sbase[tid] = (t * B_ + b) * CN_ + n;
    }

    int a_row = lane & 15;
    int a_k   = (lane >> 4) * 8;
    int b_n   = (lane & 7) + (lane >> 4) * 8;
    int b_k   = ((lane >> 3) & 1) * 8;

    float acc0[2][4][4], acc1[2][4][4];
#pragma unroll
    for (int i = 0; i < 2; ++i)
#pragma unroll
        for (int j = 0; j < 4; ++j)
#pragma unroll
            for (int r = 0; r < 4; ++r) { acc0[i][j][r] = 0.f; acc1[i][j][r] = 0.f; }

    int r8 = tid >> 3, g8 = tid & 7;

    // prologue: stage 0
    stage_load<NBP>(smt, A, APS, Bm, BPS, o0, j0, 0, r8, g8);
    CP_COMMIT();

    for (int ch = 0; ch < NCH; ++ch) {
        if (ch + 1 < NCH)
            stage_load<NBP>(smt + ((ch + 1) & 1) * STGB, A, APS, Bm, BPS,
                            o0, j0, (ch + 1) * 64, r8, g8);
        CP_COMMIT();
        CP_WAIT1();
        __syncthreads();

        unsigned sb = smt + (ch & 1) * STGB;
#pragma unroll
        for (int ks = 0; ks < 4; ++ks) {
            int k0 = ks * 16;
            unsigned ah[2][4], am[2][4];
#pragma unroll
            for (int mt = 0; mt < 2; ++mt) {
                unsigned ad = sb + (wm * 32 + mt * 16 + a_row) * TPAD + (k0 + a_k) * 2;
                ldsm4(ah[mt][0], ah[mt][1], ah[mt][2], ah[mt][3], ad);
                ldsm4(am[mt][0], am[mt][1], am[mt][2], am[mt][3], ad + ATB);
            }
            unsigned bh[2][4];
#pragma unroll
            for (int half = 0; half < 2; ++half) {
                unsigned bd = sb + 2 * ATB + (wn * 32 + half * 16 + b_n) * TPAD + (k0 + b_k) * 2;
                ldsm4(bh[half][0], bh[half][1], bh[half][2], bh[half][3], bd);
            }
            if (NBP == 2) {
                unsigned bm[2][4];
#pragma unroll
                for (int half = 0; half < 2; ++half) {
                    unsigned bd = sb + 2 * ATB + BTB + (wn * 32 + half * 16 + b_n) * TPAD + (k0 + b_k) * 2;
                    ldsm4(bm[half][0], bm[half][1], bm[half][2], bm[half][3], bd);
                }
#pragma unroll
                for (int mt = 0; mt < 2; ++mt)
#pragma unroll
                    for (int nt = 0; nt < 4; ++nt) {
                        mma16816h(acc0[mt][nt], ah[mt], &bh[nt >> 1][(nt & 1) * 2]);
                        mma16816h(acc1[mt][nt], ah[mt], &bm[nt >> 1][(nt & 1) * 2]);
                        mma16816h(acc1[mt][nt], am[mt], &bh[nt >> 1][(nt & 1) * 2]);
                    }
            } else {
#pragma unroll
                for (int mt = 0; mt < 2; ++mt)
#pragma unroll
                    for (int nt = 0; nt < 4; ++nt) {
                        mma16816h(acc0[mt][nt], ah[mt], &bh[nt >> 1][(nt & 1) * 2]);
                        mma16816h(acc1[mt][nt], am[mt], &bh[nt >> 1][(nt & 1) * 2]);
                    }
            }
        }
        __syncthreads();
    }

    // epilogue: combine scales, BN affine, store
    int p   = o0 / C_;
    int om0 = o0 - p * C_;
    float* Yp = Y + (size_t)p * TBCN;
#pragma unroll
    for (int mt = 0; mt < 2; ++mt) {
        int mbase = wm * 32 + mt * 16 + (lane >> 2);
#pragma unroll
        for (int rh = 0; rh < 2; ++rh) {
            int orow = o0 + mbase + rh * 8;
            float sc = scale[orow], bi = bias[orow];
            float* rp = Yp + (size_t)(om0 + mbase + rh * 8) * N_;
#pragma unroll
            for (int nt = 0; nt < 4; ++nt) {
                int jl = wn * 32 + nt * 8 + (lane & 3) * 2;
                float v0 = acc0[mt][nt][rh * 2 + 0] + INV2048 * acc1[mt][nt][rh * 2 + 0];
                float v1 = acc0[mt][nt][rh * 2 + 1] + INV2048 * acc1[mt][nt][rh * 2 + 1];
                rp[sbase[jl]]     = v0 * sc + bi;
                rp[sbase[jl + 1]] = v1 * sc + bi;
            }
        }
    }
}

// ---------------- LIF (sequential over T, elementwise, float4) ----------------
__global__ void lif_kernel(const float* __restrict__ in, float* __restrict__ out,
                           float thr, int total4)
{
    int i = blockIdx.x * blockDim.x + threadIdx.x;
    if (i >= total4) return;
    const int q = BCN / 4;
    int p = i / q;
    int r = i - p * q;
    const float4* ip = (const float4*)in + (size_t)p * (TBCN / 4) + r;
    float4*       op = (float4*)out      + (size_t)p * (TBCN / 4) + r;

    float4 v = make_float4(0.f, 0.f, 0.f, 0.f);
#pragma unroll
    for (int t = 0; t < T_; ++t) {
        float4 x = ip[(size_t)t * q];
        v.x += (x.x - v.x) * 0.5f;  v.y += (x.y - v.y) * 0.5f;
        v.z += (x.z - v.z) * 0.5f;  v.w += (x.w - v.w) * 0.5f;
        float4 s;
        s.x = (v.x >= thr) ? 1.0f : 0.0f;
        s.y = (v.y >= thr) ? 1.0f : 0.0f;
        s.z = (v.z >= thr) ? 1.0f : 0.0f;
        s.w = (v.w >= thr) ? 1.0f : 0.0f;
        op[(size_t)t * q] = s;
        if (s.x != 0.f) v.x = 0.f;
        if (s.y != 0.f) v.y = 0.f;
        if (s.z != 0.f) v.z = 0.f;
        if (s.w != 0.f) v.w = 0.f;
    }
}

// ---------------- Attention (per t,b,h): popcount QK^T, policy, AV ------------
__global__ __launch_bounds__(256) void attn_kernel(
    const float* __restrict__ qkv, const float* __restrict__ policy,
    float* __restrict__ out)
{
    __shared__ __align__(16) float s_v[N_ * 36];
    __shared__ unsigned s_qm[N_], s_km[N_];
    __shared__ float s_pol[N_];

    int tid = threadIdx.x;
    int bz  = blockIdx.x;            // (t*B + b)*H + h
    int h   = bz % H_;
    int tb  = bz / H_;
    int base = tb * CN_ + h * D_ * N_;

    for (int idx = tid; idx < D_ * N_; idx += 256) {
        int d = idx / N_, n = idx - d * N_;
        s_v[n * 36 + d] = qkv[base + d * N_ + n];
    }
    __syncthreads();
    int n = tid;
    if (n < N_) {
        unsigned m = 0;
#pragma unroll
        for (int d = 0; d < D_; ++d)
            if (s_v[n * 36 + d] != 0.0f) m |= (1u << d);
        s_qm[n] = m;
    }
    __syncthreads();
    for (int idx = tid; idx < D_ * N_; idx += 256) {
        int d = idx / N_, nn = idx - d * N_;
        s_v[nn * 36 + d] = qkv[TBCN + base + d * N_ + nn];
    }
    __syncthreads();
    if (n < N_) {
        unsigned m = 0;
#pragma unroll
        for (int d = 0; d < D_; ++d)
            if (s_v[n * 36 + d] != 0.0f) m |= (1u << d);
        s_km[n] = m;
    }
    __syncthreads();
    for (int idx = tid; idx < D_ * N_; idx += 256) {
        int d = idx / N_, nn = idx - d * N_;
        s_v[nn * 36 + d] = qkv[2u * TBCN + base + d * N_ + nn];
    }
    if (tid < N_) s_pol[tid] = policy[tb * N_ + tid];
    __syncthreads();

    if (n < N_) {
        unsigned long long y2[16];
#pragma unroll
        for (int i = 0; i < 16; ++i) y2[i] = 0ull;
        unsigned qm = s_qm[n];
        for (int m = 0; m < N_; ++m) {
            unsigned kmm = s_km[m];
            if (kmm == 0u) continue;          // warp-uniform skip
            int cnt = __popc(qm & kmm);
            if (cnt == 0) continue;
            float a = (float)cnt * ((m == n) ? 1.0f : s_pol[m]);
            unsigned long long aa = pack2(a, a);
            const longlong2* vp = (const longlong2*)(s_v + m * 36);
#pragma unroll
            for (int q4 = 0; q4 < 8; ++q4) {
                longlong2 vv = vp[q4];
                fma2(y2[2 * q4 + 0], aa, (unsigned long long)vv.x);
                fma2(y2[2 * q4 + 1], aa, (unsigned long long)vv.y);
            }
        }
        float* op = out + base + n;
#pragma unroll
        for (int q4 = 0; q4 < 16; ++q4) {
            float lo, hi;
            unpack2(y2[q4], lo, hi);
            op[(2 * q4 + 0) * N_] = lo * 0.25f;
            op[(2 * q4 + 1) * N_] = hi * 0.25f;
        }
    }
}

// ---------------- launch ------------------------------------------------------
extern "C" void kernel_launch(void* const* d_in, const int* in_sizes, int n_in,
                              void* d_out, int out_size)
{
    const float* x      = (const float*)d_in[0];
    const float* policy = (const float*)d_in[1];
    const float* qw = (const float*)d_in[2];
    const float* qg = (const float*)d_in[3];
    const float* qb = (const float*)d_in[4];
    const float* qm = (const float*)d_in[5];
    const float* qv = (const float*)d_in[6];
    const float* kw = (const float*)d_in[7];
    const float* kg = (const float*)d_in[8];
    const float* kb = (const float*)d_in[9];
    const float* km = (const float*)d_in[10];
    const float* kv = (const float*)d_in[11];
    const float* vw = (const float*)d_in[12];
    const float* vg = (const float*)d_in[13];
    const float* vb = (const float*)d_in[14];
    const float* vm = (const float*)d_in[15];
    const float* vv = (const float*)d_in[16];
    const float* pw = (const float*)d_in[17];
    const float* pg = (const float*)d_in[18];
    const float* pb = (const float*)d_in[19];
    const float* pm = (const float*)d_in[20];
    const float* pv = (const float*)d_in[21];
    const float* pbias = (const float*)d_in[22];

    float *qkv_p, *att_p, *bns_p, *bnb_p, *ps_p, *pbs_p;
    __half *xs_p, *ss_p, *ws_p, *pws_p;
    cudaGetSymbolAddress((void**)&qkv_p, g_qkv);
    cudaGetSymbolAddress((void**)&att_p, g_att);
    cudaGetSymbolAddress((void**)&bns_p, g_bnscale);
    cudaGetSymbolAddress((void**)&bnb_p, g_bnbias);
    cudaGetSymbolAddress((void**)&ps_p,  g_pscale);
    cudaGetSymbolAddress((void**)&pbs_p, g_pbias);
    cudaGetSymbolAddress((void**)&xs_p,  g_xs);
    cudaGetSymbolAddress((void**)&ss_p,  g_ss);
    cudaGetSymbolAddress((void**)&ws_p,  g_ws);
    cudaGetSymbolAddress((void**)&pws_p, g_ps);

    const int SM2 = 2 * (2 * ATB + 2 * BTB);   // 110592
    const int SM1 = 2 * (2 * ATB + 1 * BTB);   // 73728
    cudaFuncSetAttribute(gemm_mma<2>, cudaFuncAttributeMaxDynamicSharedMemorySize, SM2);
    cudaFuncSetAttribute(gemm_mma<1>, cudaFuncAttributeMaxDynamicSharedMemorySize, SM1);

    setup_bn<<<6, 256>>>(qg, qb, qm, qv, kg, kb, km, kv, vg, vb, vm, vv,
                         pg, pb, pm, pv, pbias);
    wsplit<<<(WQKV + WPRJ + 255) / 256, 256>>>(qw, kw, vw, pw);
    xsplit<<<dim3(JTOT / 64, C_ / 64), 256>>>(x);

    // qkv GEMM: [1152x384] @ [384x25088], fp16 2-term split (3 products)
    gemm_mma<2><<<dim3(JTOT / 128, 1152 / 64), 256, SM2>>>(
        ws_p, (size_t)WQKV, xs_p, (size_t)TBCN, bns_p, bnb_p, qkv_p);

    // LIF(theta=1) over q,k,v in place
    lif_kernel<<<(3 * BCN / 4 + 255) / 256, 256>>>(qkv_p, qkv_p, 1.0f, 3 * BCN / 4);

    // attention per (t,b,h)
    attn_kernel<<<T_ * B_ * H_, 256>>>(qkv_p, policy, att_p);

    // fused LIF(theta=0.5) + transpose -> K-major fp16 spikes
    lif_strans<<<dim3(BNJ / 64, C_ / 64), 256>>>(att_p);

    // proj GEMM: [384x384] @ [384x25088], A split, B exact (2 products) -> qkv scratch
    gemm_mma<1><<<dim3(JTOT / 128, 384 / 64), 256, SM1>>>(
        pws_p, (size_t)WPRJ, ss_p, (size_t)0, ps_p, pbs_p, qkv_p);

    // final LIF(theta=1) -> d_out
    lif_kernel<<<(BCN / 4 + 255) / 256, 256>>>(qkv_p, (float*)d_out, 1.0f, BCN / 4);
}

// round 15
// speedup vs baseline: 1.1749x; 1.1749x over previous
#include <cuda_runtime.h>
#include <cuda_fp16.h>
#include <math.h>

#define T_   4
#define B_   32
#define C_   384
#define N_   196
#define H_   12
#define D_   32
#define CN_  (C_*N_)            // 75264
#define BCN  (B_*C_*N_)         // 2408448
#define TBCN (T_*B_*C_*N_)      // 9633792
#define JTOT (B_*N_*T_)         // 25088 tokens
#define BNJ  (B_*N_)            // 6272
#define WQKV (1152*384)         // 442368
#define WPRJ (384*384)          // 147456
#define INV2048 4.8828125e-4f

// ---------------- scratch (device globals; no allocation allowed) ------------
__device__ float g_qkv[3u * TBCN];        // q,k,v spikes [p][t][b][c][n]
__device__ float g_att[TBCN];             // attention out (preact)
__device__ __half g_xs[2u * TBCN];        // split X: [part][j][c] K-major
__device__ __half g_ss[TBCN];             // proj spike input, [j][c] K-major (exact)
__device__ __half g_ws[2u * WQKV];        // split qkv weights [part][o][c]
__device__ __half g_ps[2u * WPRJ];        // split proj weights
__device__ float g_bnscale[3 * C_];
__device__ float g_bnbias[3 * C_];
__device__ float g_pscale[C_];
__device__ float g_pbias[C_];

// ---------------- helpers ------------------------------------------------------
__device__ __forceinline__ unsigned smem_to_u32(const void* p) {
    unsigned a;
    asm("{ .reg .u64 t; cvta.to.shared.u64 t, %1; cvt.u32.u64 %0, t; }"
        : "=r"(a) : "l"(p));
    return a;
}
__device__ __forceinline__ void ldsm4(unsigned& r0, unsigned& r1,
                                      unsigned& r2, unsigned& r3, unsigned addr) {
    asm volatile("ldmatrix.sync.aligned.m8n8.x4.shared.b16 {%0,%1,%2,%3}, [%4];"
        : "=r"(r0), "=r"(r1), "=r"(r2), "=r"(r3) : "r"(addr));
}
__device__ __forceinline__ void mma16816h(float* c, const unsigned* a, const unsigned* b) {
    asm volatile(
        "mma.sync.aligned.m16n8k16.row.col.f32.f16.f16.f32 "
        "{%0,%1,%2,%3}, {%4,%5,%6,%7}, {%8,%9}, {%0,%1,%2,%3};"
        : "+f"(c[0]), "+f"(c[1]), "+f"(c[2]), "+f"(c[3])
        : "r"(a[0]), "r"(a[1]), "r"(a[2]), "r"(a[3]), "r"(b[0]), "r"(b[1]));
}
__device__ __forceinline__ void cpasync16(unsigned dst, const void* src) {
    asm volatile("cp.async.cg.shared.global [%0], [%1], 16;"
        :: "r"(dst), "l"(src) : "memory");
}
#define CP_COMMIT() asm volatile("cp.async.commit_group;" ::: "memory")
#define CP_WAIT1()  asm volatile("cp.async.wait_group 1;" ::: "memory")
__device__ __forceinline__ void split2h(float x, __half& h, __half& m) {
    h = __float2half_rn(x);
    float r = x - __half2float(h);
    m = __float2half_rn(r * 2048.0f);    // scaled residual: always normal range
}
// f32x2 packed math
__device__ __forceinline__ unsigned long long pack2(float lo, float hi) {
    unsigned long long d;
    asm("mov.b64 %0, {%1, %2};" : "=l"(d) : "f"(lo), "f"(hi));
    return d;
}
__device__ __forceinline__ void fma2(unsigned long long& d,
                                     unsigned long long a, unsigned long long b) {
    asm("fma.rn.f32x2 %0, %1, %2, %3;" : "=l"(d) : "l"(a), "l"(b), "l"(d));
}
__device__ __forceinline__ void unpack2(unsigned long long v, float& lo, float& hi) {
    asm("mov.b64 {%0, %1}, %2;" : "=f"(lo), "=f"(hi) : "l"(v));
}

// ---------------- BN coefficient setup ---------------------------------------
__global__ void setup_bn(
    const float* __restrict__ qg, const float* __restrict__ qb, const float* __restrict__ qm, const float* __restrict__ qv,
    const float* __restrict__ kg, const float* __restrict__ kb, const float* __restrict__ km, const float* __restrict__ kv,
    const float* __restrict__ vg, const float* __restrict__ vb, const float* __restrict__ vm, const float* __restrict__ vv,
    const float* __restrict__ pg, const float* __restrict__ pb, const float* __restrict__ pm, const float* __restrict__ pv,
    const float* __restrict__ pbias)
{
    int i = blockIdx.x * blockDim.x + threadIdx.x;
    if (i < 3 * C_) {
        int p = i / C_, c = i - p * C_;
        const float *g, *be, *mu, *va;
        if (p == 0)      { g = qg; be = qb; mu = qm; va = qv; }
        else if (p == 1) { g = kg; be = kb; mu = km; va = kv; }
        else             { g = vg; be = vb; mu = vm; va = vv; }
        float inv = g[c] / sqrtf(va[c] + 1e-5f);
        g_bnscale[i] = inv;
        g_bnbias[i]  = be[c] - mu[c] * inv;
    } else if (i < 4 * C_) {
        int c = i - 3 * C_;
        float inv = pg[c] / sqrtf(pv[c] + 1e-5f);
        g_pscale[c] = inv;
        g_pbias[c]  = pb[c] - pm[c] * inv + pbias[c] * inv;
    }
}

// ---------------- weight split (qkv stacked 1152 rows + proj 384) -------------
__global__ void wsplit(const float* __restrict__ qw, const float* __restrict__ kw,
                       const float* __restrict__ vw, const float* __restrict__ pw)
{
    int i = blockIdx.x * blockDim.x + threadIdx.x;
    if (i < WQKV) {
        int o = i / 384, c = i - o * 384;
        const float* w = (o < 384) ? qw : ((o < 768) ? kw : vw);
        float x = w[(o % 384) * 384 + c];
        __half h, m;
        split2h(x, h, m);
        g_ws[i] = h; g_ws[WQKV + i] = m;
    } else if (i < WQKV + WPRJ) {
        int k = i - WQKV;
        __half h, m;
        split2h(pw[k], h, m);
        g_ps[k] = h; g_ps[WPRJ + k] = m;
    }
}

// ---------------- X split + transpose to [j][c] K-major -----------------------
__global__ __launch_bounds__(256) void xsplit(const float* __restrict__ X)
{
    __shared__ float tile[64 * 65];
    __shared__ int cb[64];
    int tid = threadIdx.x;
    int j0 = blockIdx.x * 64, c0 = blockIdx.y * 64;
    if (tid < 64) {
        int j = j0 + tid;
        int t = j / (B_ * N_);
        int r = j - t * (B_ * N_);
        int b = r / N_;
        int n = r - b * N_;
        cb[tid] = (t * B_ + b) * CN_ + n;
    }
    __syncthreads();
#pragma unroll
    for (int u = 0; u < 16; ++u) {
        int idx = u * 256 + tid;
        int cc = idx >> 6, jj = idx & 63;
        tile[cc * 65 + jj] = X[(size_t)cb[jj] + (size_t)(c0 + cc) * N_];
    }
    __syncthreads();
#pragma unroll
    for (int u = 0; u < 16; ++u) {
        int idx = u * 256 + tid;
        int jj = idx >> 6, cc = idx & 63;
        __half h, m;
        split2h(tile[cc * 65 + jj], h, m);
        size_t o = (size_t)(j0 + jj) * 384 + c0 + cc;
        g_xs[o] = h; g_xs[TBCN + o] = m;
    }
}

// -------- fused LIF(thr=0.5) + spike transpose to [j][c] fp16 (exact) ---------
__global__ __launch_bounds__(256) void lif_strans(const float* __restrict__ S)
{
    __shared__ float tile[64 * 65];
    __shared__ int cb[64];
    int tid = threadIdx.x;
    int bn0 = blockIdx.x * 64, c0 = blockIdx.y * 64;
    if (tid < 64) {
        int bn = bn0 + tid;
        int b = bn / N_;
        int n = bn - b * N_;
        cb[tid] = b * CN_ + n;
    }
    __syncthreads();

    float v[16];
#pragma unroll
    for (int u = 0; u < 16; ++u) v[u] = 0.0f;

    for (int t = 0; t < T_; ++t) {
        const float* St = S + (size_t)t * BCN;
#pragma unroll
        for (int u = 0; u < 16; ++u) {
            int idx = u * 256 + tid;
            int cc = idx >> 6, jj = idx & 63;
            float x = St[(size_t)cb[jj] + (size_t)(c0 + cc) * N_];
            float vv = v[u] + (x - v[u]) * 0.5f;
            float s = (vv >= 0.5f) ? 1.0f : 0.0f;
            v[u] = (s != 0.f) ? 0.f : vv;
            tile[cc * 65 + jj] = s;
        }
        __syncthreads();
        __half* out = g_ss + (size_t)(t * BNJ) * 384;
#pragma unroll
        for (int u = 0; u < 16; ++u) {
            int idx = u * 256 + tid;
            int jj = idx >> 6, cc = idx & 63;
            out[(size_t)(bn0 + jj) * 384 + c0 + cc] = __float2half_rn(tile[cc * 65 + jj]);
        }
        __syncthreads();
    }
}

// ---------------- tensor-core GEMM (fp16 2-term split) + BN + fused LIF -------
// Mainloop identical to R8 (BK=32, TPAD=80, 2-stage cp.async). Column tile =
// 32 (b,n) x 4 timesteps, so the epilogue holds all t per element and runs the
// LIF recurrence in-CTA (smem exchange across warps), writing spikes directly.
#define TPAD   80
#define ATB    (64 * TPAD)     // 5120
#define BTB    (128 * TPAD)    // 10240
#define NCH    12
#define SP     132             // epilogue smem pitch (floats)

template <int NBP>
__device__ __forceinline__ void stage_load(
    unsigned sb, const __half* __restrict__ A, size_t APS,
    const __half* __restrict__ Bm, size_t BPS,
    int o0, int bn0, int c0, int ldrow, int ldg)
{
#pragma unroll
    for (int p = 0; p < 2; ++p) {
        const __half* src = A + (size_t)p * APS + (size_t)(o0 + ldrow) * 384 + c0 + ldg * 8;
        cpasync16(sb + p * ATB + ldrow * TPAD + ldg * 16, src);
    }
#pragma unroll
    for (int p = 0; p < NBP; ++p) {
#pragma unroll
        for (int u = 0; u < 2; ++u) {
            int row = ldrow + u * 64;
            int j = (row >> 5) * BNJ + bn0 + (row & 31);
            const __half* src = Bm + (size_t)p * BPS + (size_t)j * 384 + c0 + ldg * 8;
            cpasync16(sb + 2 * ATB + p * BTB + row * TPAD + ldg * 16, src);
        }
    }
}

template <int NBP>
__global__ __launch_bounds__(256) void gemm_mma(
    const __half* __restrict__ A, size_t APS,
    const __half* __restrict__ Bm, size_t BPS,
    const float* __restrict__ scale, const float* __restrict__ bias,
    float* __restrict__ Y, float thr)
{
    constexpr int STGB = 2 * ATB + NBP * BTB;
    extern __shared__ __align__(16) char dsm[];
    unsigned smt = smem_to_u32(dsm);

    int tid = threadIdx.x;
    int wid = tid >> 5, lane = tid & 31;
    int wm = wid & 1, wn = wid >> 1;
    int bn0 = blockIdx.x * 32;
    int o0 = blockIdx.y * 64;

    int a_row = lane & 15;
    int a_k   = (lane >> 4) * 8;
    int b_n   = (lane & 7) + (lane >> 4) * 8;
    int b_k   = ((lane >> 3) & 1) * 8;

    float acc0[2][4][4], acc1[2][4][4];
#pragma unroll
    for (int i = 0; i < 2; ++i)
#pragma unroll
        for (int j = 0; j < 4; ++j)
#pragma unroll
            for (int r = 0; r < 4; ++r) { acc0[i][j][r] = 0.f; acc1[i][j][r] = 0.f; }

    int ldrow = tid >> 2, ldg = tid & 3;

    // prologue: stage 0
    stage_load<NBP>(smt, A, APS, Bm, BPS, o0, bn0, 0, ldrow, ldg);
    CP_COMMIT();

    for (int ch = 0; ch < NCH; ++ch) {
        if (ch + 1 < NCH)
            stage_load<NBP>(smt + ((ch + 1) & 1) * STGB, A, APS, Bm, BPS,
                            o0, bn0, (ch + 1) * 32, ldrow, ldg);
        CP_COMMIT();
        CP_WAIT1();
        __syncthreads();

        unsigned sb = smt + (ch & 1) * STGB;
#pragma unroll
        for (int ks = 0; ks < 2; ++ks) {
            int k0 = ks * 16;
            unsigned ah[2][4], am[2][4];
#pragma unroll
            for (int mt = 0; mt < 2; ++mt) {
                unsigned ad = sb + (wm * 32 + mt * 16 + a_row) * TPAD + (k0 + a_k) * 2;
                ldsm4(ah[mt][0], ah[mt][1], ah[mt][2], ah[mt][3], ad);
                ldsm4(am[mt][0], am[mt][1], am[mt][2], am[mt][3], ad + ATB);
            }
            unsigned bh[2][4];
#pragma unroll
            for (int half = 0; half < 2; ++half) {
                unsigned bd = sb + 2 * ATB + (wn * 32 + half * 16 + b_n) * TPAD + (k0 + b_k) * 2;
                ldsm4(bh[half][0], bh[half][1], bh[half][2], bh[half][3], bd);
            }
            if (NBP == 2) {
                unsigned bm[2][4];
#pragma unroll
                for (int half = 0; half < 2; ++half) {
                    unsigned bd = sb + 2 * ATB + BTB + (wn * 32 + half * 16 + b_n) * TPAD + (k0 + b_k) * 2;
                    ldsm4(bm[half][0], bm[half][1], bm[half][2], bm[half][3], bd);
                }
#pragma unroll
                for (int mt = 0; mt < 2; ++mt)
#pragma unroll
                    for (int nt = 0; nt < 4; ++nt) {
                        mma16816h(acc0[mt][nt], ah[mt], &bh[nt >> 1][(nt & 1) * 2]);
                        mma16816h(acc1[mt][nt], ah[mt], &bm[nt >> 1][(nt & 1) * 2]);
                        mma16816h(acc1[mt][nt], am[mt], &bh[nt >> 1][(nt & 1) * 2]);
                    }
            } else {
#pragma unroll
                for (int mt = 0; mt < 2; ++mt)
#pragma unroll
                    for (int nt = 0; nt < 4; ++nt) {
                        mma16816h(acc0[mt][nt], ah[mt], &bh[nt >> 1][(nt & 1) * 2]);
                        mma16816h(acc1[mt][nt], am[mt], &bh[nt >> 1][(nt & 1) * 2]);
                    }
            }
        }
        __syncthreads();
    }

    // ---- epilogue: BN affine -> smem [o:64][col:128] -> in-CTA LIF -> spikes
    int p   = o0 / C_;
    int om0 = o0 - p * C_;
    float* spre = (float*)dsm;
#pragma unroll
    for (int mt = 0; mt < 2; ++mt) {
#pragma unroll
        for (int rh = 0; rh < 2; ++rh) {
            int row = wm * 32 + mt * 16 + (lane >> 2) + rh * 8;
            float sc = scale[o0 + row], bi = bias[o0 + row];
#pragma unroll
            for (int nt = 0; nt < 4; ++nt) {
                int jl = wn * 32 + nt * 8 + (lane & 3) * 2;
                float v0 = acc0[mt][nt][rh * 2 + 0] + INV2048 * acc1[mt][nt][rh * 2 + 0];
                float v1 = acc0[mt][nt][rh * 2 + 1] + INV2048 * acc1[mt][nt][rh * 2 + 1];
                spre[row * SP + jl]     = v0 * sc + bi;
                spre[row * SP + jl + 1] = v1 * sc + bi;
            }
        }
    }
    __syncthreads();

#pragma unroll
    for (int u = 0; u < 8; ++u) {
        int ci = u * 256 + tid;            // 2048 chains: o(64) x bn_local(32)
        int o = ci >> 5, bnl = ci & 31;
        int bn = bn0 + bnl;
        int b = bn / N_, n = bn - b * N_;
        size_t ob = (size_t)p * TBCN + (size_t)b * CN_ + (size_t)(om0 + o) * N_ + n;
        float v = 0.0f;
#pragma unroll
        for (int t = 0; t < T_; ++t) {
            float x = spre[o * SP + t * 32 + bnl];
            v += (x - v) * 0.5f;
            float s = (v >= thr) ? 1.0f : 0.0f;
            if (s != 0.f) v = 0.f;
            Y[ob + (size_t)t * BCN] = s;
        }
    }
}

// ---------------- Attention (per t,b,h): popcount QK^T, policy, AV ------------
__global__ __launch_bounds__(256) void attn_kernel(
    const float* __restrict__ qkv, const float* __restrict__ policy,
    float* __restrict__ out)
{
    __shared__ __align__(16) float s_v[N_ * 36];
    __shared__ unsigned s_qm[N_], s_km[N_];
    __shared__ float s_pol[N_];

    int tid = threadIdx.x;
    int bz  = blockIdx.x;            // (t*B + b)*H + h
    int h   = bz % H_;
    int tb  = bz / H_;
    int base = tb * CN_ + h * D_ * N_;

    for (int idx = tid; idx < D_ * N_; idx += 256) {
        int d = idx / N_, n = idx - d * N_;
        s_v[n * 36 + d] = qkv[base + d * N_ + n];
    }
    __syncthreads();
    int n = tid;
    if (n < N_) {
        unsigned m = 0;
#pragma unroll
        for (int d = 0; d < D_; ++d)
            if (s_v[n * 36 + d] != 0.0f) m |= (1u << d);
        s_qm[n] = m;
    }
    __syncthreads();
    for (int idx = tid; idx < D_ * N_; idx += 256) {
        int d = idx / N_, nn = idx - d * N_;
        s_v[nn * 36 + d] = qkv[TBCN + base + d * N_ + nn];
    }
    __syncthreads();
    if (n < N_) {
        unsigned m = 0;
#pragma unroll
        for (int d = 0; d < D_; ++d)
            if (s_v[n * 36 + d] != 0.0f) m |= (1u << d);
        s_km[n] = m;
    }
    __syncthreads();
    for (int idx = tid; idx < D_ * N_; idx += 256) {
        int d = idx / N_, nn = idx - d * N_;
        s_v[nn * 36 + d] = qkv[2u * TBCN + base + d * N_ + nn];
    }
    if (tid < N_) s_pol[tid] = policy[tb * N_ + tid];
    __syncthreads();

    if (n < N_) {
        unsigned long long y2[16];
#pragma unroll
        for (int i = 0; i < 16; ++i) y2[i] = 0ull;
        unsigned qm = s_qm[n];
        for (int m = 0; m < N_; ++m) {
            unsigned kmm = s_km[m];
            if (kmm == 0u) continue;          // warp-uniform skip
            int cnt = __popc(qm & kmm);
            if (cnt == 0) continue;
            float a = (float)cnt * ((m == n) ? 1.0f : s_pol[m]);
            unsigned long long aa = pack2(a, a);
            const longlong2* vp = (const longlong2*)(s_v + m * 36);
#pragma unroll
            for (int q4 = 0; q4 < 8; ++q4) {
                longlong2 vv = vp[q4];
                fma2(y2[2 * q4 + 0], aa, (unsigned long long)vv.x);
                fma2(y2[2 * q4 + 1], aa, (unsigned long long)vv.y);
            }
        }
        float* op = out + base + n;
#pragma unroll
        for (int q4 = 0; q4 < 16; ++q4) {
            float lo, hi;
            unpack2(y2[q4], lo, hi);
            op[(2 * q4 + 0) * N_] = lo * 0.25f;
            op[(2 * q4 + 1) * N_] = hi * 0.25f;
        }
    }
}

// ---------------- launch ------------------------------------------------------
extern "C" void kernel_launch(void* const* d_in, const int* in_sizes, int n_in,
                              void* d_out, int out_size)
{
    const float* x      = (const float*)d_in[0];
    const float* policy = (const float*)d_in[1];
    const float* qw = (const float*)d_in[2];
    const float* qg = (const float*)d_in[3];
    const float* qb = (const float*)d_in[4];
    const float* qm = (const float*)d_in[5];
    const float* qv = (const float*)d_in[6];
    const float* kw = (const float*)d_in[7];
    const float* kg = (const float*)d_in[8];
    const float* kb = (const float*)d_in[9];
    const float* km = (const float*)d_in[10];
    const float* kv = (const float*)d_in[11];
    const float* vw = (const float*)d_in[12];
    const float* vg = (const float*)d_in[13];
    const float* vb = (const float*)d_in[14];
    const float* vm = (const float*)d_in[15];
    const float* vv = (const float*)d_in[16];
    const float* pw = (const float*)d_in[17];
    const float* pg = (const float*)d_in[18];
    const float* pb = (const float*)d_in[19];
    const float* pm = (const float*)d_in[20];
    const float* pv = (const float*)d_in[21];
    const float* pbias = (const float*)d_in[22];

    float *qkv_p, *att_p, *bns_p, *bnb_p, *ps_p, *pbs_p;
    __half *xs_p, *ss_p, *ws_p, *pws_p;
    cudaGetSymbolAddress((void**)&qkv_p, g_qkv);
    cudaGetSymbolAddress((void**)&att_p, g_att);
    cudaGetSymbolAddress((void**)&bns_p, g_bnscale);
    cudaGetSymbolAddress((void**)&bnb_p, g_bnbias);
    cudaGetSymbolAddress((void**)&ps_p,  g_pscale);
    cudaGetSymbolAddress((void**)&pbs_p, g_pbias);
    cudaGetSymbolAddress((void**)&xs_p,  g_xs);
    cudaGetSymbolAddress((void**)&ss_p,  g_ss);
    cudaGetSymbolAddress((void**)&ws_p,  g_ws);
    cudaGetSymbolAddress((void**)&pws_p, g_ps);

    const int SM2 = 2 * (2 * ATB + 2 * BTB);   // 61440
    const int SM1 = 2 * (2 * ATB + 1 * BTB);   // 40960
    cudaFuncSetAttribute(gemm_mma<2>, cudaFuncAttributeMaxDynamicSharedMemorySize, SM2);
    cudaFuncSetAttribute(gemm_mma<1>, cudaFuncAttributeMaxDynamicSharedMemorySize, SM1);

    setup_bn<<<6, 256>>>(qg, qb, qm, qv, kg, kb, km, kv, vg, vb, vm, vv,
                         pg, pb, pm, pv, pbias);
    wsplit<<<(WQKV + WPRJ + 255) / 256, 256>>>(qw, kw, vw, pw);
    xsplit<<<dim3(JTOT / 64, C_ / 64), 256>>>(x);

    // qkv GEMM + BN + fused LIF(theta=1): spikes out directly
    gemm_mma<2><<<dim3(BNJ / 32, 1152 / 64), 256, SM2>>>(
        ws_p, (size_t)WQKV, xs_p, (size_t)TBCN, bns_p, bnb_p, qkv_p, 1.0f);

    // attention per (t,b,h)
    attn_kernel<<<T_ * B_ * H_, 256>>>(qkv_p, policy, att_p);

    // fused LIF(theta=0.5) + transpose -> K-major fp16 spikes
    lif_strans<<<dim3(BNJ / 64, C_ / 64), 256>>>(att_p);

    // proj GEMM + BN + fused LIF(theta=1) -> spikes straight to d_out
    gemm_mma<1><<<dim3(BNJ / 32, 384 / 64), 256, SM1>>>(
        pws_p, (size_t)WPRJ, ss_p, (size_t)0, ps_p, pbs_p, (float*)d_out, 1.0f);
}

// round 16
// speedup vs baseline: 1.3593x; 1.1569x over previous
#include <cuda_runtime.h>
#include <cuda_fp16.h>
#include <math.h>

#define T_   4
#define B_   32
#define C_   384
#define N_   196
#define H_   12
#define D_   32
#define CN_  (C_*N_)            // 75264
#define BCN  (B_*C_*N_)         // 2408448
#define TBCN (T_*B_*C_*N_)      // 9633792
#define JTOT (B_*N_*T_)         // 25088 tokens
#define BNJ  (B_*N_)            // 6272
#define WQKV (1152*384)         // 442368
#define WPRJ (384*384)          // 147456
#define INV2048 4.8828125e-4f

// ---------------- scratch (device globals; no allocation allowed) ------------
__device__ float g_qkv[3u * TBCN];        // q,k,v spikes [p][t][b][c][n]
__device__ float g_att[TBCN];             // attention out (preact)
__device__ __half g_xs[2u * TBCN];        // split X: [part][j][c] K-major
__device__ __half g_ss[TBCN];             // proj spike input, [j][c] K-major (exact)
__device__ __half g_ws[2u * WQKV];        // split qkv weights [part][o][c]
__device__ __half g_ps[2u * WPRJ];        // split proj weights
__device__ float g_bnscale[3 * C_];
__device__ float g_bnbias[3 * C_];
__device__ float g_pscale[C_];
__device__ float g_pbias[C_];

// ---------------- helpers ------------------------------------------------------
__device__ __forceinline__ unsigned smem_to_u32(const void* p) {
    unsigned a;
    asm("{ .reg .u64 t; cvta.to.shared.u64 t, %1; cvt.u32.u64 %0, t; }"
        : "=r"(a) : "l"(p));
    return a;
}
__device__ __forceinline__ void ldsm4(unsigned& r0, unsigned& r1,
                                      unsigned& r2, unsigned& r3, unsigned addr) {
    asm volatile("ldmatrix.sync.aligned.m8n8.x4.shared.b16 {%0,%1,%2,%3}, [%4];"
        : "=r"(r0), "=r"(r1), "=r"(r2), "=r"(r3) : "r"(addr));
}
__device__ __forceinline__ void mma16816h(float* c, const unsigned* a, const unsigned* b) {
    asm volatile(
        "mma.sync.aligned.m16n8k16.row.col.f32.f16.f16.f32 "
        "{%0,%1,%2,%3}, {%4,%5,%6,%7}, {%8,%9}, {%0,%1,%2,%3};"
        : "+f"(c[0]), "+f"(c[1]), "+f"(c[2]), "+f"(c[3])
        : "r"(a[0]), "r"(a[1]), "r"(a[2]), "r"(a[3]), "r"(b[0]), "r"(b[1]));
}
__device__ __forceinline__ void cpasync16(unsigned dst, const void* src) {
    asm volatile("cp.async.cg.shared.global [%0], [%1], 16;"
        :: "r"(dst), "l"(src) : "memory");
}
#define CP_COMMIT() asm volatile("cp.async.commit_group;" ::: "memory")
#define CP_WAIT1()  asm volatile("cp.async.wait_group 1;" ::: "memory")
__device__ __forceinline__ void split2h(float x, __half& h, __half& m) {
    h = __float2half_rn(x);
    float r = x - __half2float(h);
    m = __float2half_rn(r * 2048.0f);    // scaled residual: always normal range
}
// f32x2 packed math
__device__ __forceinline__ unsigned long long pack2(float lo, float hi) {
    unsigned long long d;
    asm("mov.b64 %0, {%1, %2};" : "=l"(d) : "f"(lo), "f"(hi));
    return d;
}
__device__ __forceinline__ void fma2(unsigned long long& d,
                                     unsigned long long a, unsigned long long b) {
    asm("fma.rn.f32x2 %0, %1, %2, %3;" : "=l"(d) : "l"(a), "l"(b), "l"(d));
}
__device__ __forceinline__ void add2(unsigned long long& d, unsigned long long a) {
    asm("add.rn.f32x2 %0, %1, %2;" : "=l"(d) : "l"(d), "l"(a));
}
__device__ __forceinline__ void unpack2(unsigned long long v, float& lo, float& hi) {
    asm("mov.b64 {%0, %1}, %2;" : "=f"(lo), "=f"(hi) : "l"(v));
}

// ---------------- BN coefficient setup ---------------------------------------
__global__ void setup_bn(
    const float* __restrict__ qg, const float* __restrict__ qb, const float* __restrict__ qm, const float* __restrict__ qv,
    const float* __restrict__ kg, const float* __restrict__ kb, const float* __restrict__ km, const float* __restrict__ kv,
    const float* __restrict__ vg, const float* __restrict__ vb, const float* __restrict__ vm, const float* __restrict__ vv,
    const float* __restrict__ pg, const float* __restrict__ pb, const float* __restrict__ pm, const float* __restrict__ pv,
    const float* __restrict__ pbias)
{
    int i = blockIdx.x * blockDim.x + threadIdx.x;
    if (i < 3 * C_) {
        int p = i / C_, c = i - p * C_;
        const float *g, *be, *mu, *va;
        if (p == 0)      { g = qg; be = qb; mu = qm; va = qv; }
        else if (p == 1) { g = kg; be = kb; mu = km; va = kv; }
        else             { g = vg; be = vb; mu = vm; va = vv; }
        float inv = g[c] / sqrtf(va[c] + 1e-5f);
        g_bnscale[i] = inv;
        g_bnbias[i]  = be[c] - mu[c] * inv;
    } else if (i < 4 * C_) {
        int c = i - 3 * C_;
        float inv = pg[c] / sqrtf(pv[c] + 1e-5f);
        g_pscale[c] = inv;
        g_pbias[c]  = pb[c] - pm[c] * inv + pbias[c] * inv;
    }
}

// ---------------- weight split (qkv stacked 1152 rows + proj 384) -------------
__global__ void wsplit(const float* __restrict__ qw, const float* __restrict__ kw,
                       const float* __restrict__ vw, const float* __restrict__ pw)
{
    int i = blockIdx.x * blockDim.x + threadIdx.x;
    if (i < WQKV) {
        int o = i / 384, c = i - o * 384;
        const float* w = (o < 384) ? qw : ((o < 768) ? kw : vw);
        float x = w[(o % 384) * 384 + c];
        __half h, m;
        split2h(x, h, m);
        g_ws[i] = h; g_ws[WQKV + i] = m;
    } else if (i < WQKV + WPRJ) {
        int k = i - WQKV;
        __half h, m;
        split2h(pw[k], h, m);
        g_ps[k] = h; g_ps[WPRJ + k] = m;
    }
}

// ---------------- X split + transpose to [j][c] K-major -----------------------
__global__ __launch_bounds__(256) void xsplit(const float* __restrict__ X)
{
    __shared__ float tile[64 * 65];
    __shared__ int cb[64];
    int tid = threadIdx.x;
    int j0 = blockIdx.x * 64, c0 = blockIdx.y * 64;
    if (tid < 64) {
        int j = j0 + tid;
        int t = j / (B_ * N_);
        int r = j - t * (B_ * N_);
        int b = r / N_;
        int n = r - b * N_;
        cb[tid] = (t * B_ + b) * CN_ + n;
    }
    __syncthreads();
#pragma unroll
    for (int u = 0; u < 16; ++u) {
        int idx = u * 256 + tid;
        int cc = idx >> 6, jj = idx & 63;
        tile[cc * 65 + jj] = X[(size_t)cb[jj] + (size_t)(c0 + cc) * N_];
    }
    __syncthreads();
#pragma unroll
    for (int u = 0; u < 16; ++u) {
        int idx = u * 256 + tid;
        int jj = idx >> 6, cc = idx & 63;
        __half h, m;
        split2h(tile[cc * 65 + jj], h, m);
        size_t o = (size_t)(j0 + jj) * 384 + c0 + cc;
        g_xs[o] = h; g_xs[TBCN + o] = m;
    }
}

// -------- fused LIF(thr=0.5) + spike transpose to [j][c] fp16 (exact) ---------
__global__ __launch_bounds__(256) void lif_strans(const float* __restrict__ S)
{
    __shared__ float tile[64 * 65];
    __shared__ int cb[64];
    int tid = threadIdx.x;
    int bn0 = blockIdx.x * 64, c0 = blockIdx.y * 64;
    if (tid < 64) {
        int bn = bn0 + tid;
        int b = bn / N_;
        int n = bn - b * N_;
        cb[tid] = b * CN_ + n;
    }
    __syncthreads();

    float v[16];
#pragma unroll
    for (int u = 0; u < 16; ++u) v[u] = 0.0f;

    for (int t = 0; t < T_; ++t) {
        const float* St = S + (size_t)t * BCN;
#pragma unroll
        for (int u = 0; u < 16; ++u) {
            int idx = u * 256 + tid;
            int cc = idx >> 6, jj = idx & 63;
            float x = St[(size_t)cb[jj] + (size_t)(c0 + cc) * N_];
            float vv = v[u] + (x - v[u]) * 0.5f;
            float s = (vv >= 0.5f) ? 1.0f : 0.0f;
            v[u] = (s != 0.f) ? 0.f : vv;
            tile[cc * 65 + jj] = s;
        }
        __syncthreads();
        __half* out = g_ss + (size_t)(t * BNJ) * 384;
#pragma unroll
        for (int u = 0; u < 16; ++u) {
            int idx = u * 256 + tid;
            int jj = idx >> 6, cc = idx & 63;
            out[(size_t)(bn0 + jj) * 384 + c0 + cc] = __float2half_rn(tile[cc * 65 + jj]);
        }
        __syncthreads();
    }
}

// ---------------- tensor-core GEMM (fp16 2-term split) + BN + fused LIF -------
#define TPAD   80
#define ATB    (64 * TPAD)     // 5120
#define BTB    (128 * TPAD)    // 10240
#define NCH    12
#define SP     132             // epilogue smem pitch (floats)

template <int NBP>
__device__ __forceinline__ void stage_load(
    unsigned sb, const __half* __restrict__ A, size_t APS,
    const __half* __restrict__ Bm, size_t BPS,
    int o0, int bn0, int c0, int ldrow, int ldg)
{
#pragma unroll
    for (int p = 0; p < 2; ++p) {
        const __half* src = A + (size_t)p * APS + (size_t)(o0 + ldrow) * 384 + c0 + ldg * 8;
        cpasync16(sb + p * ATB + ldrow * TPAD + ldg * 16, src);
    }
#pragma unroll
    for (int p = 0; p < NBP; ++p) {
#pragma unroll
        for (int u = 0; u < 2; ++u) {
            int row = ldrow + u * 64;
            int j = (row >> 5) * BNJ + bn0 + (row & 31);
            const __half* src = Bm + (size_t)p * BPS + (size_t)j * 384 + c0 + ldg * 8;
            cpasync16(sb + 2 * ATB + p * BTB + row * TPAD + ldg * 16, src);
        }
    }
}

template <int NBP>
__global__ __launch_bounds__(256) void gemm_mma(
    const __half* __restrict__ A, size_t APS,
    const __half* __restrict__ Bm, size_t BPS,
    const float* __restrict__ scale, const float* __restrict__ bias,
    float* __restrict__ Y, float thr)
{
    constexpr int STGB = 2 * ATB + NBP * BTB;
    extern __shared__ __align__(16) char dsm[];
    unsigned smt = smem_to_u32(dsm);

    int tid = threadIdx.x;
    int wid = tid >> 5, lane = tid & 31;
    int wm = wid & 1, wn = wid >> 1;
    int bn0 = blockIdx.x * 32;
    int o0 = blockIdx.y * 64;

    int a_row = lane & 15;
    int a_k   = (lane >> 4) * 8;
    int b_n   = (lane & 7) + (lane >> 4) * 8;
    int b_k   = ((lane >> 3) & 1) * 8;

    float acc0[2][4][4], acc1[2][4][4];
#pragma unroll
    for (int i = 0; i < 2; ++i)
#pragma unroll
        for (int j = 0; j < 4; ++j)
#pragma unroll
            for (int r = 0; r < 4; ++r) { acc0[i][j][r] = 0.f; acc1[i][j][r] = 0.f; }

    int ldrow = tid >> 2, ldg = tid & 3;

    // prologue: stage 0
    stage_load<NBP>(smt, A, APS, Bm, BPS, o0, bn0, 0, ldrow, ldg);
    CP_COMMIT();

    for (int ch = 0; ch < NCH; ++ch) {
        if (ch + 1 < NCH)
            stage_load<NBP>(smt + ((ch + 1) & 1) * STGB, A, APS, Bm, BPS,
                            o0, bn0, (ch + 1) * 32, ldrow, ldg);
        CP_COMMIT();
        CP_WAIT1();
        __syncthreads();

        unsigned sb = smt + (ch & 1) * STGB;
#pragma unroll
        for (int ks = 0; ks < 2; ++ks) {
            int k0 = ks * 16;
            unsigned ah[2][4], am[2][4];
#pragma unroll
            for (int mt = 0; mt < 2; ++mt) {
                unsigned ad = sb + (wm * 32 + mt * 16 + a_row) * TPAD + (k0 + a_k) * 2;
                ldsm4(ah[mt][0], ah[mt][1], ah[mt][2], ah[mt][3], ad);
                ldsm4(am[mt][0], am[mt][1], am[mt][2], am[mt][3], ad + ATB);
            }
            unsigned bh[2][4];
#pragma unroll
            for (int half = 0; half < 2; ++half) {
                unsigned bd = sb + 2 * ATB + (wn * 32 + half * 16 + b_n) * TPAD + (k0 + b_k) * 2;
                ldsm4(bh[half][0], bh[half][1], bh[half][2], bh[half][3], bd);
            }
            if (NBP == 2) {
                unsigned bm[2][4];
#pragma unroll
                for (int half = 0; half < 2; ++half) {
                    unsigned bd = sb + 2 * ATB + BTB + (wn * 32 + half * 16 + b_n) * TPAD + (k0 + b_k) * 2;
                    ldsm4(bm[half][0], bm[half][1], bm[half][2], bm[half][3], bd);
                }
#pragma unroll
                for (int mt = 0; mt < 2; ++mt)
#pragma unroll
                    for (int nt = 0; nt < 4; ++nt) {
                        mma16816h(acc0[mt][nt], ah[mt], &bh[nt >> 1][(nt & 1) * 2]);
                        mma16816h(acc1[mt][nt], ah[mt], &bm[nt >> 1][(nt & 1) * 2]);
                        mma16816h(acc1[mt][nt], am[mt], &bh[nt >> 1][(nt & 1) * 2]);
                    }
            } else {
#pragma unroll
                for (int mt = 0; mt < 2; ++mt)
#pragma unroll
                    for (int nt = 0; nt < 4; ++nt) {
                        mma16816h(acc0[mt][nt], ah[mt], &bh[nt >> 1][(nt & 1) * 2]);
                        mma16816h(acc1[mt][nt], am[mt], &bh[nt >> 1][(nt & 1) * 2]);
                    }
            }
        }
        __syncthreads();
    }

    // ---- epilogue: BN affine -> smem [o:64][col:128] -> in-CTA LIF -> spikes
    int p   = o0 / C_;
    int om0 = o0 - p * C_;
    float* spre = (float*)dsm;
#pragma unroll
    for (int mt = 0; mt < 2; ++mt) {
#pragma unroll
        for (int rh = 0; rh < 2; ++rh) {
            int row = wm * 32 + mt * 16 + (lane >> 2) + rh * 8;
            float sc = scale[o0 + row], bi = bias[o0 + row];
#pragma unroll
            for (int nt = 0; nt < 4; ++nt) {
                int jl = wn * 32 + nt * 8 + (lane & 3) * 2;
                float v0 = acc0[mt][nt][rh * 2 + 0] + INV2048 * acc1[mt][nt][rh * 2 + 0];
                float v1 = acc0[mt][nt][rh * 2 + 1] + INV2048 * acc1[mt][nt][rh * 2 + 1];
                spre[row * SP + jl]     = v0 * sc + bi;
                spre[row * SP + jl + 1] = v1 * sc + bi;
            }
        }
    }
    __syncthreads();

#pragma unroll
    for (int u = 0; u < 8; ++u) {
        int ci = u * 256 + tid;            // 2048 chains: o(64) x bn_local(32)
        int o = ci >> 5, bnl = ci & 31;
        int bn = bn0 + bnl;
        int b = bn / N_, n = bn - b * N_;
        size_t ob = (size_t)p * TBCN + (size_t)b * CN_ + (size_t)(om0 + o) * N_ + n;
        float v = 0.0f;
#pragma unroll
        for (int t = 0; t < T_; ++t) {
            float x = spre[o * SP + t * 32 + bnl];
            v += (x - v) * 0.5f;
            float s = (v >= thr) ? 1.0f : 0.0f;
            if (s != 0.f) v = 0.f;
            Y[ob + (size_t)t * BCN] = s;
        }
    }
}

// ---------------- Attention (per t,b,h) — factored form -----------------------
// y(n,d) = sum_e qbit(n,e) * Z(e,d) + popc(qm&km)(n) * (1-pol(n)) * vbit(n,d)
// where Z(e,d) = sum_m kbit(m,e) * pol(m) * vbit(m,d)  (32x32 per block).
__global__ __launch_bounds__(256) void attn_kernel(
    const float* __restrict__ qkv, const float* __restrict__ policy,
    float* __restrict__ out)
{
    __shared__ unsigned s_qm[N_], s_km[N_], s_vm[N_];
    __shared__ float s_pol[N_];
    __shared__ __align__(16) float s_Z[32][36];   // [e][d], rows 16B-aligned

    int tid = threadIdx.x;
    int bz  = blockIdx.x;            // (t*B + b)*H + h
    int h   = bz % H_;
    int tb  = bz / H_;
    int base = tb * CN_ + h * D_ * N_;

    // ---- build bitmasks directly from gmem (coalesced across n per d) ----
    for (int n = tid; n < N_; n += 256) {
        unsigned qm = 0, km = 0, vm = 0;
        const float* qp = qkv + base + n;
        const float* kp = qkv + TBCN + base + n;
        const float* vp = qkv + 2u * TBCN + base + n;
#pragma unroll
        for (int d = 0; d < D_; ++d) {
            if (qp[d * N_] != 0.0f) qm |= (1u << d);
            if (kp[d * N_] != 0.0f) km |= (1u << d);
            if (vp[d * N_] != 0.0f) vm |= (1u << d);
        }
        s_qm[n] = qm; s_km[n] = km; s_vm[n] = vm;
        s_pol[n] = policy[tb * N_ + n];
    }
    __syncthreads();

    // ---- phase 1: Z[e][d]; lane = e, warp w covers d in [4w, 4w+4) ----
    {
        int e = tid & 31;
        int wd = (tid >> 5) * 4;
        float z0 = 0.f, z1 = 0.f, z2 = 0.f, z3 = 0.f;
        for (int m = 0; m < N_; ++m) {
            unsigned km = s_km[m];
            if ((km >> e) & 1u) {
                unsigned vsh = s_vm[m] >> wd;
                float pm = s_pol[m];
                z0 += (vsh & 1u) ? pm : 0.f;
                z1 += (vsh & 2u) ? pm : 0.f;
                z2 += (vsh & 4u) ? pm : 0.f;
                z3 += (vsh & 8u) ? pm : 0.f;
            }
        }
        s_Z[e][wd + 0] = z0;
        s_Z[e][wd + 1] = z1;
        s_Z[e][wd + 2] = z2;
        s_Z[e][wd + 3] = z3;
    }
    __syncthreads();

    // ---- phase 2: y(n,:) = sum over set e-bits of qm(n) of Z[e][:] + diag ----
    int n = tid;
    if (n < N_) {
        unsigned long long y2[16];
#pragma unroll
        for (int i = 0; i < 16; ++i) y2[i] = 0ull;
        unsigned qm = s_qm[n];
        for (int e = 0; e < 32; ++e) {
            if ((qm >> e) & 1u) {
                const longlong2* zp = (const longlong2*)s_Z[e];
#pragma unroll
                for (int q4 = 0; q4 < 8; ++q4) {
                    longlong2 zz = zp[q4];
                    add2(y2[2 * q4 + 0], (unsigned long long)zz.x);
                    add2(y2[2 * q4 + 1], (unsigned long long)zz.y);
                }
            }
        }
        // diagonal correction
        int cnt = __popc(qm & s_km[n]);
        float coef = (float)cnt * (1.0f - s_pol[n]);
        unsigned vm = s_vm[n];

        float* op = out + base + n;
#pragma unroll
        for (int q4 = 0; q4 < 16; ++q4) {
            float lo, hi;
            unpack2(y2[q4], lo, hi);
            lo += ((vm >> (2 * q4)) & 1u) ? coef : 0.f;
            hi += ((vm >> (2 * q4 + 1)) & 1u) ? coef : 0.f;
            op[(2 * q4 + 0) * N_] = lo * 0.25f;
            op[(2 * q4 + 1) * N_] = hi * 0.25f;
        }
    }
}

// ---------------- launch ------------------------------------------------------
extern "C" void kernel_launch(void* const* d_in, const int* in_sizes, int n_in,
                              void* d_out, int out_size)
{
    const float* x      = (const float*)d_in[0];
    const float* policy = (const float*)d_in[1];
    const float* qw = (const float*)d_in[2];
    const float* qg = (const float*)d_in[3];
    const float* qb = (const float*)d_in[4];
    const float* qm = (const float*)d_in[5];
    const float* qv = (const float*)d_in[6];
    const float* kw = (const float*)d_in[7];
    const float* kg = (const float*)d_in[8];
    const float* kb = (const float*)d_in[9];
    const float* km = (const float*)d_in[10];
    const float* kv = (const float*)d_in[11];
    const float* vw = (const float*)d_in[12];
    const float* vg = (const float*)d_in[13];
    const float* vb = (const float*)d_in[14];
    const float* vm = (const float*)d_in[15];
    const float* vv = (const float*)d_in[16];
    const float* pw = (const float*)d_in[17];
    const float* pg = (const float*)d_in[18];
    const float* pb = (const float*)d_in[19];
    const float* pm = (const float*)d_in[20];
    const float* pv = (const float*)d_in[21];
    const float* pbias = (const float*)d_in[22];

    float *qkv_p, *att_p, *bns_p, *bnb_p, *ps_p, *pbs_p;
    __half *xs_p, *ss_p, *ws_p, *pws_p;
    cudaGetSymbolAddress((void**)&qkv_p, g_qkv);
    cudaGetSymbolAddress((void**)&att_p, g_att);
    cudaGetSymbolAddress((void**)&bns_p, g_bnscale);
    cudaGetSymbolAddress((void**)&bnb_p, g_bnbias);
    cudaGetSymbolAddress((void**)&ps_p,  g_pscale);
    cudaGetSymbolAddress((void**)&pbs_p, g_pbias);
    cudaGetSymbolAddress((void**)&xs_p,  g_xs);
    cudaGetSymbolAddress((void**)&ss_p,  g_ss);
    cudaGetSymbolAddress((void**)&ws_p,  g_ws);
    cudaGetSymbolAddress((void**)&pws_p, g_ps);

    const int SM2 = 2 * (2 * ATB + 2 * BTB);   // 61440
    const int SM1 = 2 * (2 * ATB + 1 * BTB);   // 40960
    cudaFuncSetAttribute(gemm_mma<2>, cudaFuncAttributeMaxDynamicSharedMemorySize, SM2);
    cudaFuncSetAttribute(gemm_mma<1>, cudaFuncAttributeMaxDynamicSharedMemorySize, SM1);

    setup_bn<<<6, 256>>>(qg, qb, qm, qv, kg, kb, km, kv, vg, vb, vm, vv,
                         pg, pb, pm, pv, pbias);
    wsplit<<<(WQKV + WPRJ + 255) / 256, 256>>>(qw, kw, vw, pw);
    xsplit<<<dim3(JTOT / 64, C_ / 64), 256>>>(x);

    // qkv GEMM + BN + fused LIF(theta=1): spikes out directly
    gemm_mma<2><<<dim3(BNJ / 32, 1152 / 64), 256, SM2>>>(
        ws_p, (size_t)WQKV, xs_p, (size_t)TBCN, bns_p, bnb_p, qkv_p, 1.0f);

    // attention per (t,b,h) — factored q(k^T diag(pol) v) form
    attn_kernel<<<T_ * B_ * H_, 256>>>(qkv_p, policy, att_p);

    // fused LIF(theta=0.5) + transpose -> K-major fp16 spikes
    lif_strans<<<dim3(BNJ / 64, C_ / 64), 256>>>(att_p);

    // proj GEMM + BN + fused LIF(theta=1) -> spikes straight to d_out
    gemm_mma<1><<<dim3(BNJ / 32, 384 / 64), 256, SM1>>>(
        pws_p, (size_t)WPRJ, ss_p, (size_t)0, ps_p, pbs_p, (float*)d_out, 1.0f);
}

// round 17
// speedup vs baseline: 1.4195x; 1.0443x over previous
#include <cuda_runtime.h>
#include <cuda_fp16.h>
#include <math.h>

#define T_   4
#define B_   32
#define C_   384
#define N_   196
#define H_   12
#define D_   32
#define CN_  (C_*N_)            // 75264
#define BCN  (B_*C_*N_)         // 2408448
#define TBCN (T_*B_*C_*N_)      // 9633792
#define JTOT (B_*N_*T_)         // 25088 tokens
#define BNJ  (B_*N_)            // 6272
#define WQKV (1152*384)         // 442368
#define WPRJ (384*384)          // 147456

// ---------------- scratch (device globals; no allocation allowed) ------------
__device__ float g_qkv[3u * TBCN];        // q,k,v spikes [p][t][b][c][n]
__device__ float g_att[TBCN];             // attention out (preact)
__device__ __half g_xs[2u * TBCN];        // split X: [part][j][c] K-major
__device__ __half g_ss[TBCN];             // proj spike input, [j][c] K-major (exact)
__device__ __half g_ws[2u * WQKV];        // split qkv weights [part][o][c]
__device__ __half g_ps[2u * WPRJ];        // split proj weights
__device__ float g_bnscale[3 * C_];
__device__ float g_bnbias[3 * C_];
__device__ float g_pscale[C_];
__device__ float g_pbias[C_];

// ---------------- helpers ------------------------------------------------------
__device__ __forceinline__ unsigned smem_to_u32(const void* p) {
    unsigned a;
    asm("{ .reg .u64 t; cvta.to.shared.u64 t, %1; cvt.u32.u64 %0, t; }"
        : "=r"(a) : "l"(p));
    return a;
}
__device__ __forceinline__ void ldsm4(unsigned& r0, unsigned& r1,
                                      unsigned& r2, unsigned& r3, unsigned addr) {
    asm volatile("ldmatrix.sync.aligned.m8n8.x4.shared.b16 {%0,%1,%2,%3}, [%4];"
        : "=r"(r0), "=r"(r1), "=r"(r2), "=r"(r3) : "r"(addr));
}
__device__ __forceinline__ void mma16816h(float* c, const unsigned* a, const unsigned* b) {
    asm volatile(
        "mma.sync.aligned.m16n8k16.row.col.f32.f16.f16.f32 "
        "{%0,%1,%2,%3}, {%4,%5,%6,%7}, {%8,%9}, {%0,%1,%2,%3};"
        : "+f"(c[0]), "+f"(c[1]), "+f"(c[2]), "+f"(c[3])
        : "r"(a[0]), "r"(a[1]), "r"(a[2]), "r"(a[3]), "r"(b[0]), "r"(b[1]));
}
__device__ __forceinline__ void cpasync16(unsigned dst, const void* src) {
    asm volatile("cp.async.cg.shared.global [%0], [%1], 16;"
        :: "r"(dst), "l"(src) : "memory");
}
#define CP_COMMIT() asm volatile("cp.async.commit_group;" ::: "memory")
#define CP_WAIT1()  asm volatile("cp.async.wait_group 1;" ::: "memory")
// split: h = fp16(x); m = fp16(x - h) UNSCALED (subnormals OK on tensor cores;
// identical bits to the scaled variant whenever the residual is fp16-normal).
__device__ __forceinline__ void split2h(float x, __half& h, __half& m) {
    h = __float2half_rn(x);
    m = __float2half_rn(x - __half2float(h));
}
// f32x2 packed math
__device__ __forceinline__ void add2(unsigned long long& d, unsigned long long a) {
    asm("add.rn.f32x2 %0, %1, %2;" : "=l"(d) : "l"(d), "l"(a));
}
__device__ __forceinline__ void unpack2(unsigned long long v, float& lo, float& hi) {
    asm("mov.b64 {%0, %1}, %2;" : "=f"(lo), "=f"(hi) : "l"(v));
}

// ---------------- BN coefficient setup ---------------------------------------
__global__ void setup_bn(
    const float* __restrict__ qg, const float* __restrict__ qb, const float* __restrict__ qm, const float* __restrict__ qv,
    const float* __restrict__ kg, const float* __restrict__ kb, const float* __restrict__ km, const float* __restrict__ kv,
    const float* __restrict__ vg, const float* __restrict__ vb, const float* __restrict__ vm, const float* __restrict__ vv,
    const float* __restrict__ pg, const float* __restrict__ pb, const float* __restrict__ pm, const float* __restrict__ pv,
    const float* __restrict__ pbias)
{
    int i = blockIdx.x * blockDim.x + threadIdx.x;
    if (i < 3 * C_) {
        int p = i / C_, c = i - p * C_;
        const float *g, *be, *mu, *va;
        if (p == 0)      { g = qg; be = qb; mu = qm; va = qv; }
        else if (p == 1) { g = kg; be = kb; mu = km; va = kv; }
        else             { g = vg; be = vb; mu = vm; va = vv; }
        float inv = g[c] / sqrtf(va[c] + 1e-5f);
        g_bnscale[i] = inv;
        g_bnbias[i]  = be[c] - mu[c] * inv;
    } else if (i < 4 * C_) {
        int c = i - 3 * C_;
        float inv = pg[c] / sqrtf(pv[c] + 1e-5f);
        g_pscale[c] = inv;
        g_pbias[c]  = pb[c] - pm[c] * inv + pbias[c] * inv;
    }
}

// ---------------- weight split (qkv stacked 1152 rows + proj 384) -------------
__global__ void wsplit(const float* __restrict__ qw, const float* __restrict__ kw,
                       const float* __restrict__ vw, const float* __restrict__ pw)
{
    int i = blockIdx.x * blockDim.x + threadIdx.x;
    if (i < WQKV) {
        int o = i / 384, c = i - o * 384;
        const float* w = (o < 384) ? qw : ((o < 768) ? kw : vw);
        float x = w[(o % 384) * 384 + c];
        __half h, m;
        split2h(x, h, m);
        g_ws[i] = h; g_ws[WQKV + i] = m;
    } else if (i < WQKV + WPRJ) {
        int k = i - WQKV;
        __half h, m;
        split2h(pw[k], h, m);
        g_ps[k] = h; g_ps[WPRJ + k] = m;
    }
}

// ---------------- X split + transpose to [j][c] K-major -----------------------
__global__ __launch_bounds__(256) void xsplit(const float* __restrict__ X)
{
    __shared__ float tile[64 * 65];
    __shared__ int cb[64];
    int tid = threadIdx.x;
    int j0 = blockIdx.x * 64, c0 = blockIdx.y * 64;
    if (tid < 64) {
        int j = j0 + tid;
        int t = j / (B_ * N_);
        int r = j - t * (B_ * N_);
        int b = r / N_;
        int n = r - b * N_;
        cb[tid] = (t * B_ + b) * CN_ + n;
    }
    __syncthreads();
#pragma unroll
    for (int u = 0; u < 16; ++u) {
        int idx = u * 256 + tid;
        int cc = idx >> 6, jj = idx & 63;
        tile[cc * 65 + jj] = X[(size_t)cb[jj] + (size_t)(c0 + cc) * N_];
    }
    __syncthreads();
#pragma unroll
    for (int u = 0; u < 16; ++u) {
        int idx = u * 256 + tid;
        int jj = idx >> 6, cc = idx & 63;
        __half h, m;
        split2h(tile[cc * 65 + jj], h, m);
        size_t o = (size_t)(j0 + jj) * 384 + c0 + cc;
        g_xs[o] = h; g_xs[TBCN + o] = m;
    }
}

// -------- fused LIF(thr=0.5) + spike transpose to [j][c] fp16 (exact) ---------
__global__ __launch_bounds__(256) void lif_strans(const float* __restrict__ S)
{
    __shared__ float tile[64 * 65];
    __shared__ int cb[64];
    int tid = threadIdx.x;
    int bn0 = blockIdx.x * 64, c0 = blockIdx.y * 64;
    if (tid < 64) {
        int bn = bn0 + tid;
        int b = bn / N_;
        int n = bn - b * N_;
        cb[tid] = b * CN_ + n;
    }
    __syncthreads();

    float v[16];
#pragma unroll
    for (int u = 0; u < 16; ++u) v[u] = 0.0f;

    for (int t = 0; t < T_; ++t) {
        const float* St = S + (size_t)t * BCN;
#pragma unroll
        for (int u = 0; u < 16; ++u) {
            int idx = u * 256 + tid;
            int cc = idx >> 6, jj = idx & 63;
            float x = St[(size_t)cb[jj] + (size_t)(c0 + cc) * N_];
            float vv = v[u] + (x - v[u]) * 0.5f;
            float s = (vv >= 0.5f) ? 1.0f : 0.0f;
            v[u] = (s != 0.f) ? 0.f : vv;
            tile[cc * 65 + jj] = s;
        }
        __syncthreads();
        __half* out = g_ss + (size_t)(t * BNJ) * 384;
#pragma unroll
        for (int u = 0; u < 16; ++u) {
            int idx = u * 256 + tid;
            int jj = idx >> 6, cc = idx & 63;
            out[(size_t)(bn0 + jj) * 384 + c0 + cc] = __float2half_rn(tile[cc * 65 + jj]);
        }
        __syncthreads();
    }
}

// ---------------- tensor-core GEMM (fp16 split, single accumulator) -----------
// acc += Wh*Xh + Wh*Xm + Wm*Xh  (residuals stored unscaled -> one fp32 acc).
// Mainloop structure = R8/R15 (BK=32, TPAD=80, 2-stage cp.async).
// Column tile = 32 (b,n) x 4 timesteps; epilogue runs LIF in-CTA, writes spikes.
#define TPAD   80
#define ATB    (64 * TPAD)     // 5120
#define BTB    (128 * TPAD)    // 10240
#define NCH    12
#define SP     132             // epilogue smem pitch (floats)

template <int NBP>
__device__ __forceinline__ void stage_load(
    unsigned sb, const __half* __restrict__ A, size_t APS,
    const __half* __restrict__ Bm, size_t BPS,
    int o0, int bn0, int c0, int ldrow, int ldg)
{
#pragma unroll
    for (int p = 0; p < 2; ++p) {
        const __half* src = A + (size_t)p * APS + (size_t)(o0 + ldrow) * 384 + c0 + ldg * 8;
        cpasync16(sb + p * ATB + ldrow * TPAD + ldg * 16, src);
    }
#pragma unroll
    for (int p = 0; p < NBP; ++p) {
#pragma unroll
        for (int u = 0; u < 2; ++u) {
            int row = ldrow + u * 64;
            int j = (row >> 5) * BNJ + bn0 + (row & 31);
            const __half* src = Bm + (size_t)p * BPS + (size_t)j * 384 + c0 + ldg * 8;
            cpasync16(sb + 2 * ATB + p * BTB + row * TPAD + ldg * 16, src);
        }
    }
}

template <int NBP>
__global__ __launch_bounds__(256, 3) void gemm_mma(
    const __half* __restrict__ A, size_t APS,
    const __half* __restrict__ Bm, size_t BPS,
    const float* __restrict__ scale, const float* __restrict__ bias,
    float* __restrict__ Y, float thr)
{
    constexpr int STGB = 2 * ATB + NBP * BTB;
    extern __shared__ __align__(16) char dsm[];
    unsigned smt = smem_to_u32(dsm);

    int tid = threadIdx.x;
    int wid = tid >> 5, lane = tid & 31;
    int wm = wid & 1, wn = wid >> 1;
    int bn0 = blockIdx.x * 32;
    int o0 = blockIdx.y * 64;

    int a_row = lane & 15;
    int a_k   = (lane >> 4) * 8;
    int b_n   = (lane & 7) + (lane >> 4) * 8;
    int b_k   = ((lane >> 3) & 1) * 8;

    float acc[2][4][4];
#pragma unroll
    for (int i = 0; i < 2; ++i)
#pragma unroll
        for (int j = 0; j < 4; ++j)
#pragma unroll
            for (int r = 0; r < 4; ++r) acc[i][j][r] = 0.f;

    int ldrow = tid >> 2, ldg = tid & 3;

    // prologue: stage 0
    stage_load<NBP>(smt, A, APS, Bm, BPS, o0, bn0, 0, ldrow, ldg);
    CP_COMMIT();

    for (int ch = 0; ch < NCH; ++ch) {
        if (ch + 1 < NCH)
            stage_load<NBP>(smt + ((ch + 1) & 1) * STGB, A, APS, Bm, BPS,
                            o0, bn0, (ch + 1) * 32, ldrow, ldg);
        CP_COMMIT();
        CP_WAIT1();
        __syncthreads();

        unsigned sb = smt + (ch & 1) * STGB;
#pragma unroll
        for (int ks = 0; ks < 2; ++ks) {
            int k0 = ks * 16;
            unsigned ah[2][4], am[2][4];
#pragma unroll
            for (int mt = 0; mt < 2; ++mt) {
                unsigned ad = sb + (wm * 32 + mt * 16 + a_row) * TPAD + (k0 + a_k) * 2;
                ldsm4(ah[mt][0], ah[mt][1], ah[mt][2], ah[mt][3], ad);
                ldsm4(am[mt][0], am[mt][1], am[mt][2], am[mt][3], ad + ATB);
            }
            unsigned bh[2][4];
#pragma unroll
            for (int half = 0; half < 2; ++half) {
                unsigned bd = sb + 2 * ATB + (wn * 32 + half * 16 + b_n) * TPAD + (k0 + b_k) * 2;
                ldsm4(bh[half][0], bh[half][1], bh[half][2], bh[half][3], bd);
            }
            if (NBP == 2) {
                unsigned bm[2][4];
#pragma unroll
                for (int half = 0; half < 2; ++half) {
                    unsigned bd = sb + 2 * ATB + BTB + (wn * 32 + half * 16 + b_n) * TPAD + (k0 + b_k) * 2;
                    ldsm4(bm[half][0], bm[half][1], bm[half][2], bm[half][3], bd);
                }
#pragma unroll
                for (int mt = 0; mt < 2; ++mt)
#pragma unroll
                    for (int nt = 0; nt < 4; ++nt) {
                        mma16816h(acc[mt][nt], ah[mt], &bh[nt >> 1][(nt & 1) * 2]);
                        mma16816h(acc[mt][nt], ah[mt], &bm[nt >> 1][(nt & 1) * 2]);
                        mma16816h(acc[mt][nt], am[mt], &bh[nt >> 1][(nt & 1) * 2]);
                    }
            } else {
#pragma unroll
                for (int mt = 0; mt < 2; ++mt)
#pragma unroll
                    for (int nt = 0; nt < 4; ++nt) {
                        mma16816h(acc[mt][nt], ah[mt], &bh[nt >> 1][(nt & 1) * 2]);
                        mma16816h(acc[mt][nt], am[mt], &bh[nt >> 1][(nt & 1) * 2]);
                    }
            }
        }
        __syncthreads();
    }

    // ---- epilogue: BN affine -> smem [o:64][col:128] -> in-CTA LIF -> spikes
    int p   = o0 / C_;
    int om0 = o0 - p * C_;
    float* spre = (float*)dsm;
#pragma unroll
    for (int mt = 0; mt < 2; ++mt) {
#pragma unroll
        for (int rh = 0; rh < 2; ++rh) {
            int row = wm * 32 + mt * 16 + (lane >> 2) + rh * 8;
            float sc = scale[o0 + row], bi = bias[o0 + row];
#pragma unroll
            for (int nt = 0; nt < 4; ++nt) {
                int jl = wn * 32 + nt * 8 + (lane & 3) * 2;
                spre[row * SP + jl]     = acc[mt][nt][rh * 2 + 0] * sc + bi;
                spre[row * SP + jl + 1] = acc[mt][nt][rh * 2 + 1] * sc + bi;
            }
        }
    }
    __syncthreads();

#pragma unroll
    for (int u = 0; u < 8; ++u) {
        int ci = u * 256 + tid;            // 2048 chains: o(64) x bn_local(32)
        int o = ci >> 5, bnl = ci & 31;
        int bn = bn0 + bnl;
        int b = bn / N_, n = bn - b * N_;
        size_t ob = (size_t)p * TBCN + (size_t)b * CN_ + (size_t)(om0 + o) * N_ + n;
        float v = 0.0f;
#pragma unroll
        for (int t = 0; t < T_; ++t) {
            float x = spre[o * SP + t * 32 + bnl];
            v += (x - v) * 0.5f;
            float s = (v >= thr) ? 1.0f : 0.0f;
            if (s != 0.f) v = 0.f;
            Y[ob + (size_t)t * BCN] = s;
        }
    }
}

// ---------------- Attention (per t,b,h) — factored form -----------------------
// y(n,d) = sum_e qbit(n,e) * Z(e,d) + popc(qm&km)(n) * (1-pol(n)) * vbit(n,d)
// where Z(e,d) = sum_m kbit(m,e) * pol(m) * vbit(m,d)  (32x32 per block).
__global__ __launch_bounds__(256) void attn_kernel(
    const float* __restrict__ qkv, const float* __restrict__ policy,
    float* __restrict__ out)
{
    __shared__ unsigned s_qm[N_], s_km[N_], s_vm[N_];
    __shared__ float s_pol[N_];
    __shared__ __align__(16) float s_Z[32][36];   // [e][d], rows 16B-aligned

    int tid = threadIdx.x;
    int bz  = blockIdx.x;            // (t*B + b)*H + h
    int h   = bz % H_;
    int tb  = bz / H_;
    int base = tb * CN_ + h * D_ * N_;

    // ---- build bitmasks directly from gmem (coalesced across n per d) ----
    for (int n = tid; n < N_; n += 256) {
        unsigned qm = 0, km = 0, vm = 0;
        const float* qp = qkv + base + n;
        const float* kp = qkv + TBCN + base + n;
        const float* vp = qkv + 2u * TBCN + base + n;
#pragma unroll
        for (int d = 0; d < D_; ++d) {
            if (qp[d * N_] != 0.0f) qm |= (1u << d);
            if (kp[d * N_] != 0.0f) km |= (1u << d);
            if (vp[d * N_] != 0.0f) vm |= (1u << d);
        }
        s_qm[n] = qm; s_km[n] = km; s_vm[n] = vm;
        s_pol[n] = policy[tb * N_ + n];
    }
    __syncthreads();

    // ---- phase 1: Z[e][d]; lane = e, warp w covers d in [4w, 4w+4) ----
    {
        int e = tid & 31;
        int wd = (tid >> 5) * 4;
        float z0 = 0.f, z1 = 0.f, z2 = 0.f, z3 = 0.f;
        for (int m = 0; m < N_; ++m) {
            unsigned km = s_km[m];
            if ((km >> e) & 1u) {
                unsigned vsh = s_vm[m] >> wd;
                float pm = s_pol[m];
                z0 += (vsh & 1u) ? pm : 0.f;
                z1 += (vsh & 2u) ? pm : 0.f;
                z2 += (vsh & 4u) ? pm : 0.f;
                z3 += (vsh & 8u) ? pm : 0.f;
            }
        }
        s_Z[e][wd + 0] = z0;
        s_Z[e][wd + 1] = z1;
        s_Z[e][wd + 2] = z2;
        s_Z[e][wd + 3] = z3;
    }
    __syncthreads();

    // ---- phase 2: y(n,:) = sum over set e-bits of qm(n) of Z[e][:] + diag ----
    int n = tid;
    if (n < N_) {
        unsigned long long y2[16];
#pragma unroll
        for (int i = 0; i < 16; ++i) y2[i] = 0ull;
        unsigned qm = s_qm[n];
        for (int e = 0; e < 32; ++e) {
            if ((qm >> e) & 1u) {
                const longlong2* zp = (const longlong2*)s_Z[e];
#pragma unroll
                for (int q4 = 0; q4 < 8; ++q4) {
                    longlong2 zz = zp[q4];
                    add2(y2[2 * q4 + 0], (unsigned long long)zz.x);
                    add2(y2[2 * q4 + 1], (unsigned long long)zz.y);
                }
            }
        }
        // diagonal correction
        int cnt = __popc(qm & s_km[n]);
        float coef = (float)cnt * (1.0f - s_pol[n]);
        unsigned vm = s_vm[n];

        float* op = out + base + n;
#pragma unroll
        for (int q4 = 0; q4 < 16; ++q4) {
            float lo, hi;
            unpack2(y2[q4], lo, hi);
            lo += ((vm >> (2 * q4)) & 1u) ? coef : 0.f;
            hi += ((vm >> (2 * q4 + 1)) & 1u) ? coef : 0.f;
            op[(2 * q4 + 0) * N_] = lo * 0.25f;
            op[(2 * q4 + 1) * N_] = hi * 0.25f;
        }
    }
}

// ---------------- launch ------------------------------------------------------
extern "C" void kernel_launch(void* const* d_in, const int* in_sizes, int n_in,
                              void* d_out, int out_size)
{
    const float* x      = (const float*)d_in[0];
    const float* policy = (const float*)d_in[1];
    const float* qw = (const float*)d_in[2];
    const float* qg = (const float*)d_in[3];
    const float* qb = (const float*)d_in[4];
    const float* qm = (const float*)d_in[5];
    const float* qv = (const float*)d_in[6];
    const float* kw = (const float*)d_in[7];
    const float* kg = (const float*)d_in[8];
    const float* kb = (const float*)d_in[9];
    const float* km = (const float*)d_in[10];
    const float* kv = (const float*)d_in[11];
    const float* vw = (const float*)d_in[12];
    const float* vg = (const float*)d_in[13];
    const float* vb = (const float*)d_in[14];
    const float* vm = (const float*)d_in[15];
    const float* vv = (const float*)d_in[16];
    const float* pw = (const float*)d_in[17];
    const float* pg = (const float*)d_in[18];
    const float* pb = (const float*)d_in[19];
    const float* pm = (const float*)d_in[20];
    const float* pv = (const float*)d_in[21];
    const float* pbias = (const float*)d_in[22];

    float *qkv_p, *att_p, *bns_p, *bnb_p, *ps_p, *pbs_p;
    __half *xs_p, *ss_p, *ws_p, *pws_p;
    cudaGetSymbolAddress((void**)&qkv_p, g_qkv);
    cudaGetSymbolAddress((void**)&att_p, g_att);
    cudaGetSymbolAddress((void**)&bns_p, g_bnscale);
    cudaGetSymbolAddress((void**)&bnb_p, g_bnbias);
    cudaGetSymbolAddress((void**)&ps_p,  g_pscale);
    cudaGetSymbolAddress((void**)&pbs_p, g_pbias);
    cudaGetSymbolAddress((void**)&xs_p,  g_xs);
    cudaGetSymbolAddress((void**)&ss_p,  g_ss);
    cudaGetSymbolAddress((void**)&ws_p,  g_ws);
    cudaGetSymbolAddress((void**)&pws_p, g_ps);

    const int SM2 = 2 * (2 * ATB + 2 * BTB);   // 61440
    const int SM1 = 2 * (2 * ATB + 1 * BTB);   // 40960
    cudaFuncSetAttribute(gemm_mma<2>, cudaFuncAttributeMaxDynamicSharedMemorySize, SM2);
    cudaFuncSetAttribute(gemm_mma<1>, cudaFuncAttributeMaxDynamicSharedMemorySize, SM1);

    setup_bn<<<6, 256>>>(qg, qb, qm, qv, kg, kb, km, kv, vg, vb, vm, vv,
                         pg, pb, pm, pv, pbias);
    wsplit<<<(WQKV + WPRJ + 255) / 256, 256>>>(qw, kw, vw, pw);
    xsplit<<<dim3(JTOT / 64, C_ / 64), 256>>>(x);

    // qkv GEMM + BN + fused LIF(theta=1): spikes out directly
    gemm_mma<2><<<dim3(BNJ / 32, 1152 / 64), 256, SM2>>>(
        ws_p, (size_t)WQKV, xs_p, (size_t)TBCN, bns_p, bnb_p, qkv_p, 1.0f);

    // attention per (t,b,h) — factored q(k^T diag(pol) v) form
    attn_kernel<<<T_ * B_ * H_, 256>>>(qkv_p, policy, att_p);

    // fused LIF(theta=0.5) + transpose -> K-major fp16 spikes
    lif_strans<<<dim3(BNJ / 64, C_ / 64), 256>>>(att_p);

    // proj GEMM + BN + fused LIF(theta=1) -> spikes straight to d_out
    gemm_mma<1><<<dim3(BNJ / 32, 384 / 64), 256, SM1>>>(
        pws_p, (size_t)WPRJ, ss_p, (size_t)0, ps_p, pbs_p, (float*)d_out, 1.0f);
}